// round 2
// baseline (speedup 1.0000x reference)
#include <cuda_runtime.h>
#include <cuda_bf16.h>

// Problem constants (from reference): B=128, T=200, V=10, F=256
#define V 10
#define VV 100
#define F 256
#define F4 64            // F/4
#define ROW4 640         // V*F/4 float4 per graph
#define NTHREADS 128

__global__ __launch_bounds__(NTHREADS, 8)
void graph_embed_kernel(const float* __restrict__ end_output,
                        const float* __restrict__ S,
                        const float* __restrict__ mul,
                        const float* __restrict__ bias,
                        const float* __restrict__ means,
                        const float* __restrict__ stds,
                        const float* __restrict__ emb_in,
                        const float* __restrict__ emb_out,
                        const float* __restrict__ emb3,
                        const float* __restrict__ emb4,
                        float* __restrict__ out,        // outputs part
                        float* __restrict__ out_att)    // atten_bias part
{
    const int g   = blockIdx.x;      // graph index in [0, B*T)
    const int tid = threadIdx.x;

    __shared__ float ds[VV];         // symmetrized S, then FW dist (in-place)
    __shared__ float muls[VV], biass[VV], m3[VV], m4[VV];
    __shared__ float meanss[V], stdss[V];
    __shared__ int   Dsh[V];
    __shared__ int   si[VV], ei[VV];

    const float* Sg = S + (size_t)g * VV;

    int i = 0, j = 0;
    if (tid < VV) {
        i = tid / V; j = tid % V;
        // symmetrize: min(S[i,j], S[j,i])
        float a_ = Sg[tid];
        float b_ = Sg[j * V + i];
        ds[tid]    = fminf(a_, b_);
        muls[tid]  = mul[tid];
        biass[tid] = bias[tid];
        m3[tid]    = emb3[tid];
        m4[tid]    = emb4[tid];
    }
    if (tid < V) {
        meanss[tid] = means[tid];
        stdss[tid]  = stds[tid];
    }
    __syncthreads();

    // --- edge_feature = tanh(sigmoid(gauss(S@mul + bias))) ---
    float ef = 0.0f, spv = 0.0f, dsown = 0.0f;
    if (tid < VV) {
        float x = biass[tid];
        #pragma unroll
        for (int m = 0; m < V; m++)
            x += ds[i * V + m] * muls[m * V + j];
        float sd = stdss[j];
        float z  = (x - meanss[j]) / sd;
        const float a = sqrtf(2.0f * 3.14159f);   // PI as written in the source
        float tmp = expf(-0.5f * z * z) / (a * sd);
        float sg  = 1.0f / (1.0f + expf(-tmp));
        ef = tanhf(sg);
        dsown = ds[tid];
    }
    // --- degree: D[j] = sum_i ds[i,j] (before FW mutates ds) ---
    if (tid < V) {
        float dsum = 0.0f;
        #pragma unroll
        for (int ii = 0; ii < V; ii++) dsum += ds[ii * V + tid];
        Dsh[tid] = (int)dsum;   // trunc toward zero, dsum >= 0
    }
    __syncthreads();

    // --- Floyd-Warshall with update-indicator accumulation ---
    #pragma unroll
    for (int k = 0; k < V; k++) {
        float dik = 0.0f, dkj = 0.0f;
        if (tid < VV) { dik = ds[i * V + k]; dkj = ds[k * V + j]; }
        __syncthreads();
        if (tid < VV) {
            float temp = dik + dkj;
            if (temp < dsown) {          // == (new != dist)
                dsown = temp;
                ds[tid] = temp;
                spv += ef;
            }
        }
        __syncthreads();
    }

    // --- integer indices for the two gather encodings ---
    if (tid < VV) {
        int Si = (int)dsown;  Si = min(max(Si, 0), V - 1);
        int Ei = (int)spv;    Ei = min(max(Ei, 0), V - 1);
        si[tid] = Si;
        ei[tid] =Ei;
    }
    __syncthreads();

    // --- atten_bias[g, i, c] = sum_j ( emb3[si[i,j], c] + emb4[ei[i,j], c] )
    //     (reference sums axis=-2 of the (B,T,i,j,10) gather == sum over j) ---
    if (tid < VV) {
        int ii = tid / V, c = tid % V;
        float acc = 0.0f;
        #pragma unroll
        for (int jj = 0; jj < V; jj++) {
            acc += m3[si[ii * V + jj] * V + c];
            acc += m4[ei[ii * V + jj] * V + c];
        }
        out_att[(size_t)g * VV + tid] = acc;
    }

    // --- big streaming phase: outputs = end_output + emb_in[Di] + emb_out[Di] ---
    const float4* eo4   = (const float4*)(end_output + (size_t)g * (V * F));
    float4*       o4    = (float4*)(out + (size_t)g * (V * F));
    const float4* ein4  = (const float4*)emb_in;
    const float4* eout4 = (const float4*)emb_out;
    #pragma unroll
    for (int it = 0; it < ROW4 / NTHREADS; it++) {
        int idx = tid + it * NTHREADS;     // 0..639
        int v   = idx >> 6;                // /F4
        int f4  = idx & (F4 - 1);
        int d   = Dsh[v];
        float4 e  = eo4[idx];
        float4 a1 = __ldg(&ein4[d * F4 + f4]);
        float4 a2 = __ldg(&eout4[d * F4 + f4]);
        float4 r;
        r.x = e.x + a1.x + a2.x;
        r.y = e.y + a1.y + a2.y;
        r.z = e.z + a1.z + a2.z;
        r.w = e.w + a1.w + a2.w;
        o4[idx] = r;
    }
}

extern "C" void kernel_launch(void* const* d_in, const int* in_sizes, int n_in,
                              void* d_out, int out_size)
{
    const float* end_output = (const float*)d_in[0];   // (B,T,V,F)
    const float* S          = (const float*)d_in[1];   // (B,T,V,V)
    const float* mul_       = (const float*)d_in[2];   // (V,V)
    const float* bias_      = (const float*)d_in[3];   // (V,V)
    const float* means_     = (const float*)d_in[4];   // (1,V)
    const float* stds_      = (const float*)d_in[5];   // (1,V)
    const float* emb_in_    = (const float*)d_in[6];   // (F,F)
    const float* emb_out_   = (const float*)d_in[7];   // (F,F)
    const float* emb3_      = (const float*)d_in[8];   // (V,V)
    const float* emb4_      = (const float*)d_in[9];   // (V,V)

    float* out = (float*)d_out;
    const int graphs = in_sizes[1] / VV;               // B*T
    float* out_att = out + (size_t)in_sizes[0];        // atten_bias after outputs

    graph_embed_kernel<<<graphs, NTHREADS>>>(
        end_output, S, mul_, bias_, means_, stds_,
        emb_in_, emb_out_, emb3_, emb4_, out, out_att);
}